// round 9
// baseline (speedup 1.0000x reference)
#include <cuda_runtime.h>
#include <math.h>

#define MARGIN 0.2f
#define EPS_V  1e-6f
#define ENC(i) (0x7FFFFFFF - (i))

// Packed accumulator: bits[0:38) sum_q (fixed-point 2^16),
//                     bits[38:52) valid count, bits[52:63) done-block count.
#define SUM_BITS   38
#define CNT_SHIFT  38
#define DONE_SHIFT 52
#define SUM_MASK   ((1ull << SUM_BITS) - 1ull)
#define CNT_MASK   ((1ull << (DONE_SHIFT - CNT_SHIFT)) - 1ull)
#define FIXP       65536.0

// Zero-init at load; last triplet block resets everything each run so every
// graph replay sees identical initial state.
__device__ int                g_first_enc[256];  // 0 = absent; else ENC(first idx)
__device__ int                g_mfirst_enc;      // 0 = all labels identical
__device__ unsigned long long g_acc;             // packed sum|cnt|done

// ---------------------------------------------------------------------------
// K1: multi-block prep. Global atomics spread across L2.
// ---------------------------------------------------------------------------
__global__ void __launch_bounds__(256) prep_kernel(const int* __restrict__ label, int B) {
    const int i    = blockIdx.x * 256 + threadIdx.x;
    const int lane = threadIdx.x & 31;
    const int l0   = __ldg(&label[0]);

    const int lab = (i < B) ? __ldg(&label[i]) : l0;
    if (i < B)
        atomicMax(&g_first_enc[lab & 255], ENC(i));

    unsigned m = __ballot_sync(0xffffffffu, (i < B) && (lab != l0));
    if (lane == 0 && m) {
        int j = (i - lane) + __ffs(m) - 1;
        atomicMax(&g_mfirst_enc, ENC(j));
    }
}

// ---------------------------------------------------------------------------
// K2: one warp per row. The a-row streams via cp.async.cg -> SMEM (no register
// cost, bypasses L1 so pos/neg rows stay L1-hot, deep MLP). Single-atomic
// deterministic reduction tail (no fences -> no L1 flush).
// ---------------------------------------------------------------------------
__global__ void __launch_bounds__(256, 6) triplet_kernel(const float* __restrict__ z,
                                                         const int* __restrict__ label,
                                                         const int* __restrict__ zidx,
                                                         float* __restrict__ out,
                                                         int B, int C, int k,
                                                         unsigned int nblocks) {
    __shared__ float s_a[8 * 1024];   // 8 warps x 4KB a-row
    const int warp = threadIdx.x >> 5;
    const int lane = threadIdx.x & 31;
    const int i = blockIdx.x * 8 + warp;

    const bool fast = (C == 1024) && (i < B);

    // ---- independent of prep: stream the a-row into SMEM via cp.async.cg ----
    if (fast) {
        const char* agm = (const char*)(z + (size_t)i * 1024);
        unsigned int sbase = (unsigned int)__cvta_generic_to_shared(
            &s_a[warp * 1024]);
        #pragma unroll
        for (int u = 0; u < 8; u++) {
            unsigned int saddr = sbase + (unsigned int)((lane + (u << 5)) * 16);
            const char* gaddr = agm + (lane + (u << 5)) * 16;
            asm volatile("cp.async.cg.shared.global [%0], [%1], 16;\n"
                         :: "r"(saddr), "l"(gaddr));
        }
        asm volatile("cp.async.commit_group;\n" ::: "memory");
    }
    const int lab_i = (i < B) ? __ldg(&label[i]) : 0;
    const int l0    = __ldg(&label[0]);
    const int idx_i = (i < B) ? __ldg(&zidx[i]) : 0;

    // ---- wait for prep ----
    cudaGridDependencySynchronize();

    float per = 0.0f;
    unsigned int vld = 0u;

    if (i < B) {
        const bool allsame = (g_mfirst_enc == 0);
        int pos = -1, neg = -1;

        if (!allsame) {
            const int f = 0x7FFFFFFF - g_first_enc[lab_i & 255];
            if (f != i) {
                pos = f;
                if (__ldg(&zidx[f]) == idx_i) pos = -1;   // degenerate zidx dup
            }
            if (pos < 0) {
                // i is the first occurrence: scan forward for the 2nd (rare)
                for (int base = i + 1; base < B; base += 32) {
                    int j = base + lane;
                    bool ok = false;
                    if (j < B)
                        ok = (__ldg(&label[j]) == lab_i) && (__ldg(&zidx[j]) != idx_i);
                    unsigned m = __ballot_sync(0xffffffffu, ok);
                    if (m) { pos = base + __ffs(m) - 1; break; }
                }
            }
            neg = (lab_i != l0) ? 0 : (0x7FFFFFFF - g_mfirst_enc);
        } else {
            // all labels equal: effective labels are -1 for j<k, l0 otherwise
            if (i < k) { pos = (i == 0) ? 1 : 0;       neg = k; }
            else       { pos = (i == k) ? (k + 1) : k; neg = 0; }
            if (pos >= B || neg >= B || k < 2) { pos = -1; }
        }

        if (pos >= 0 && pos < B && neg >= 0 && neg < B) {
            const float4* p = (const float4*)(z + (size_t)pos * C);
            const float4* n = (const float4*)(z + (size_t)neg * C);
            float sap = 0.0f, san = 0.0f;

            if (fast) {
                asm volatile("cp.async.wait_group 0;\n" ::: "memory");
                const float4* as = (const float4*)&s_a[warp * 1024];
                #pragma unroll
                for (int u = 0; u < 8; u++) {
                    const int v = lane + (u << 5);
                    float4 avv = as[v];        // LDS.128, conflict-free
                    float4 pv = __ldg(&p[v]);
                    float4 nv = __ldg(&n[v]);
                    float d;
                    d = avv.x - pv.x + EPS_V; sap = fmaf(d, d, sap);
                    d = avv.y - pv.y + EPS_V; sap = fmaf(d, d, sap);
                    d = avv.z - pv.z + EPS_V; sap = fmaf(d, d, sap);
                    d = avv.w - pv.w + EPS_V; sap = fmaf(d, d, sap);
                    d = avv.x - nv.x + EPS_V; san = fmaf(d, d, san);
                    d = avv.y - nv.y + EPS_V; san = fmaf(d, d, san);
                    d = avv.z - nv.z + EPS_V; san = fmaf(d, d, san);
                    d = avv.w - nv.w + EPS_V; san = fmaf(d, d, san);
                }
            } else {
                const float* a = z + (size_t)i * C;
                const int nvec = C >> 2;
                const float4* a4 = (const float4*)a;
                for (int v = lane; v < nvec; v += 32) {
                    float4 avv = __ldcs(&a4[v]);
                    float4 pv = __ldg(&p[v]);
                    float4 nv = __ldg(&n[v]);
                    float d;
                    d = avv.x - pv.x + EPS_V; sap = fmaf(d, d, sap);
                    d = avv.y - pv.y + EPS_V; sap = fmaf(d, d, sap);
                    d = avv.z - pv.z + EPS_V; sap = fmaf(d, d, sap);
                    d = avv.w - pv.w + EPS_V; sap = fmaf(d, d, sap);
                    d = avv.x - nv.x + EPS_V; san = fmaf(d, d, san);
                    d = avv.y - nv.y + EPS_V; san = fmaf(d, d, san);
                    d = avv.z - nv.z + EPS_V; san = fmaf(d, d, san);
                    d = avv.w - nv.w + EPS_V; san = fmaf(d, d, san);
                }
            }
            #pragma unroll
            for (int o = 16; o > 0; o >>= 1) {
                sap += __shfl_xor_sync(0xffffffffu, sap, o);
                san += __shfl_xor_sync(0xffffffffu, san, o);
            }
            per = fmaxf(sqrtf(sap) - sqrtf(san) + MARGIN, 0.0f);
            vld = 1u;
        } else if (fast) {
            asm volatile("cp.async.wait_group 0;\n" ::: "memory");
        }
    } else if (fast) {
        asm volatile("cp.async.wait_group 0;\n" ::: "memory");
    }

    // ---- single-atomic deterministic tail ----
    __shared__ float s_s[8];
    __shared__ unsigned int s_c[8];
    __shared__ bool s_last;
    __shared__ unsigned long long s_total;
    if (lane == 0) { s_s[warp] = per; s_c[warp] = vld; }
    __syncthreads();
    if (threadIdx.x == 0) {
        double bsum = 0.0; unsigned int c = 0u;
        #pragma unroll
        for (int w = 0; w < 8; w++) { bsum += (double)s_s[w]; c += s_c[w]; }
        unsigned long long q = (unsigned long long)(bsum * FIXP + 0.5);
        unsigned long long val = q
                               | ((unsigned long long)c << CNT_SHIFT)
                               | (1ull << DONE_SHIFT);
        unsigned long long old = atomicAdd(&g_acc, val);   // relaxed, no fence
        s_last  = ((old >> DONE_SHIFT) == (unsigned long long)(nblocks - 1u));
        s_total = old + val;
    }
    __syncthreads();
    if (!s_last) return;

    // last block: the packed word already holds the final sums
    if (threadIdx.x == 0) {
        unsigned long long t = s_total;
        unsigned long long sq = t & SUM_MASK;
        unsigned int c = (unsigned int)((t >> CNT_SHIFT) & CNT_MASK);
        out[0] = (c > 0u) ? (float)(((double)sq / FIXP) / (double)c) : 0.0f;
        g_acc = 0ull;
        g_mfirst_enc = 0;
    }
    g_first_enc[threadIdx.x] = 0;   // 256 threads reset the table
}

extern "C" void kernel_launch(void* const* d_in, const int* in_sizes, int n_in,
                              void* d_out, int out_size) {
    const int* z_label = (const int*)d_in[0];
    const int* z_idx   = (const int*)d_in[1];
    const float* z     = (const float*)d_in[2];
    float* out = (float*)d_out;

    const int B = in_sizes[0];
    const int C = in_sizes[2] / B;
    int k = (int)((double)B * 0.01);
    if (k < 2) k = 2;

    const int prep_blocks = (B + 255) / 256;
    prep_kernel<<<prep_blocks, 256>>>(z_label, B);

    const unsigned int nblocks = (unsigned int)((B + 7) / 8);
    {
        cudaLaunchConfig_t cfg = {};
        cfg.gridDim = dim3(nblocks);
        cfg.blockDim = dim3(256);
        cfg.dynamicSmemBytes = 0;
        cfg.stream = 0;
        cudaLaunchAttribute at[1];
        at[0].id = cudaLaunchAttributeProgrammaticStreamSerialization;
        at[0].val.programmaticStreamSerializationAllowed = 1;
        cfg.attrs = at;
        cfg.numAttrs = 1;
        cudaLaunchKernelEx(&cfg, triplet_kernel, z, z_label, z_idx, out, B, C, k, nblocks);
    }
}